// round 1
// baseline (speedup 1.0000x reference)
#include <cuda_runtime.h>

#define NATOM 131072
#define MNBR  12
#define ORIGF 92
#define NBRF  41
#define AF    64
#define C2    128      // 2*AF
#define FIN   169      // 2*AF + NBRF
#define NSEG  1024
#define NCONVL 3
#define NMROWS (NATOM*MNBR)   // 1572864
#define EPSBN 1e-5f

// ------------------------- static device scratch -------------------------
__device__ float  g_x[NATOM*AF];                    // current atom features
__device__ float  g_A1[NATOM*C2];                   // self contribution + bias
__device__ float  g_P [NATOM*C2];                   // neighbor contribution
__device__ float  g_gated[(size_t)NMROWS*C2];       // pre-BN conv output (805MB)
__device__ float  g_s[NATOM*AF];                    // summed messages
__device__ double g_stats[384];                     // [0:128) sum1, [128:256) sq1, [256:320) sum2, [320:384) sq2
__device__ float  g_scale1[C2], g_shift1[C2];
__device__ float  g_scale2[AF], g_shift2[AF];
__device__ float  g_pool[NSEG*AF];
__device__ float  g_cnt[NSEG];

// ------------------------- math helpers -------------------------
__device__ __forceinline__ float softplusf_(float x) {
    if (x > 15.0f) return x;
    return log1pf(__expf(x));
}
__device__ __forceinline__ float sigmoidf_(float x) {
    return 1.0f / (1.0f + __expf(-x));
}

// ------------------------- embed: g_x = atom_fea @ W_embed + b -------------------------
__global__ void embed_kernel(const float* __restrict__ A,
                             const float* __restrict__ W,
                             const float* __restrict__ b) {
    __shared__ float As[128][96];
    __shared__ float Ws[92][64];
    const int tid  = threadIdx.x;
    const int row0 = blockIdx.x * 128;
    for (int i = tid; i < 128 * 92; i += 256) {
        int r = i / 92, k = i - r * 92;
        As[r][k] = A[(size_t)(row0 + r) * 92 + k];
    }
    for (int i = tid; i < 92 * 64; i += 256) Ws[i >> 6][i & 63] = W[i];
    __syncthreads();
    const int ty = tid >> 4, tx = tid & 15;
    float acc[8][4];
#pragma unroll
    for (int i = 0; i < 8; i++) { acc[i][0]=0.f; acc[i][1]=0.f; acc[i][2]=0.f; acc[i][3]=0.f; }
    for (int k = 0; k < 92; k++) {
        float av[8];
#pragma unroll
        for (int i = 0; i < 8; i++) av[i] = As[ty * 8 + i][k];
        float4 bv = *(const float4*)&Ws[k][tx * 4];
#pragma unroll
        for (int i = 0; i < 8; i++) {
            acc[i][0] += av[i] * bv.x; acc[i][1] += av[i] * bv.y;
            acc[i][2] += av[i] * bv.z; acc[i][3] += av[i] * bv.w;
        }
    }
    float4 bb = *(const float4*)&b[tx * 4];
#pragma unroll
    for (int i = 0; i < 8; i++) {
        float4 o;
        o.x = acc[i][0] + bb.x; o.y = acc[i][1] + bb.y;
        o.z = acc[i][2] + bb.z; o.w = acc[i][3] + bb.w;
        *(float4*)&g_x[(size_t)(row0 + ty * 8 + i) * 64 + tx * 4] = o;
    }
}

// ------------------------- self/nbr GEMMs: A1 = X@W[0:64]+b ; P = X@W[64:128] ---------
__global__ void selfnbr_kernel(const float* __restrict__ convW,
                               const float* __restrict__ convb, int l) {
    __shared__ float Xs[128][68];
    __shared__ float Ws[64][128];
    const int tid  = threadIdx.x;
    const int row0 = blockIdx.x * 128;
    const int half = blockIdx.y;   // 0: self -> g_A1(+bias), 1: nbr -> g_P
    const float* W = convW + ((size_t)l * FIN + half * 64) * C2;
    for (int i = tid; i < 128 * 64; i += 256) {
        int r = i >> 6, k = i & 63;
        Xs[r][k] = g_x[(size_t)(row0 + r) * 64 + k];
    }
    for (int i = tid; i < 64 * 128; i += 256) Ws[i >> 7][i & 127] = W[i];
    __syncthreads();
    const int ty = tid >> 4, tx = tid & 15;
    float acc[8][8];
#pragma unroll
    for (int i = 0; i < 8; i++)
#pragma unroll
        for (int j = 0; j < 8; j++) acc[i][j] = 0.f;
    for (int k = 0; k < 64; k++) {
        float av[8];
#pragma unroll
        for (int i = 0; i < 8; i++) av[i] = Xs[ty * 8 + i][k];
        float4 b0 = *(const float4*)&Ws[k][tx * 8];
        float4 b1 = *(const float4*)&Ws[k][tx * 8 + 4];
#pragma unroll
        for (int i = 0; i < 8; i++) {
            acc[i][0] += av[i] * b0.x; acc[i][1] += av[i] * b0.y;
            acc[i][2] += av[i] * b0.z; acc[i][3] += av[i] * b0.w;
            acc[i][4] += av[i] * b1.x; acc[i][5] += av[i] * b1.y;
            acc[i][6] += av[i] * b1.z; acc[i][7] += av[i] * b1.w;
        }
    }
    float* dst = half ? g_P : g_A1;
    float4 c0 = {0.f,0.f,0.f,0.f}, c1 = {0.f,0.f,0.f,0.f};
    if (!half) {
        c0 = *(const float4*)&convb[l * C2 + tx * 8];
        c1 = *(const float4*)&convb[l * C2 + tx * 8 + 4];
    }
#pragma unroll
    for (int i = 0; i < 8; i++) {
        size_t base = (size_t)(row0 + ty * 8 + i) * C2 + tx * 8;
        float4 o0, o1;
        o0.x = acc[i][0] + c0.x; o0.y = acc[i][1] + c0.y;
        o0.z = acc[i][2] + c0.z; o0.w = acc[i][3] + c0.w;
        o1.x = acc[i][4] + c1.x; o1.y = acc[i][5] + c1.y;
        o1.z = acc[i][6] + c1.z; o1.w = acc[i][7] + c1.w;
        *(float4*)&dst[base]     = o0;
        *(float4*)&dst[base + 4] = o1;
    }
}

// ------------------------- zero stats -------------------------
__global__ void zstats_kernel() {
    if (threadIdx.x < 384) g_stats[threadIdx.x] = 0.0;
}

// ------------------------- main conv: gated = edge@We + A1[n] + P[idx] ; BN1 stats ----
__global__ void convmain_kernel(const float* __restrict__ nbr_fea,
                                const int* __restrict__ nbr_idx,
                                const float* __restrict__ convW, int l) {
    __shared__ float Es[128][44];
    __shared__ float Ws[41][128];
    __shared__ int   s_idx[128];
    __shared__ float bred[8][128];
    const int tid = threadIdx.x;
    const int r0  = blockIdx.x * 128;
    const float* We = convW + ((size_t)l * FIN + 128) * C2;
    for (int i = tid; i < 128 * 41; i += 256) {
        int r = i / 41, k = i - r * 41;
        Es[r][k] = nbr_fea[(size_t)r0 * 41 + i];
    }
    for (int i = tid; i < 41 * 128; i += 256) Ws[i >> 7][i & 127] = We[i];
    if (tid < 128) s_idx[tid] = nbr_idx[r0 + tid];
    __syncthreads();
    const int ty = tid >> 4, tx = tid & 15;
    float acc[8][8];
#pragma unroll
    for (int i = 0; i < 8; i++)
#pragma unroll
        for (int j = 0; j < 8; j++) acc[i][j] = 0.f;
    for (int k = 0; k < 41; k++) {
        float av[8];
#pragma unroll
        for (int i = 0; i < 8; i++) av[i] = Es[ty * 8 + i][k];
        float4 b0 = *(const float4*)&Ws[k][tx * 8];
        float4 b1 = *(const float4*)&Ws[k][tx * 8 + 4];
#pragma unroll
        for (int i = 0; i < 8; i++) {
            acc[i][0] += av[i] * b0.x; acc[i][1] += av[i] * b0.y;
            acc[i][2] += av[i] * b0.z; acc[i][3] += av[i] * b0.w;
            acc[i][4] += av[i] * b1.x; acc[i][5] += av[i] * b1.y;
            acc[i][6] += av[i] * b1.z; acc[i][7] += av[i] * b1.w;
        }
    }
    // epilogue: add gathered per-atom terms, store gated, accumulate BN1 stats
    float csum[8], csq[8];
#pragma unroll
    for (int j = 0; j < 8; j++) { csum[j] = 0.f; csq[j] = 0.f; }
    const int cbase = tx * 8;
#pragma unroll
    for (int i = 0; i < 8; i++) {
        int r  = ty * 8 + i;
        int gr = r0 + r;
        int n  = gr / MNBR;
        const float* arow = g_A1 + (size_t)n * C2;
        const float* prow = g_P  + (size_t)s_idx[r] * C2;
        float4 a0 = *(const float4*)&arow[cbase];
        float4 a1 = *(const float4*)&arow[cbase + 4];
        float4 p0 = *(const float4*)&prow[cbase];
        float4 p1 = *(const float4*)&prow[cbase + 4];
        float v[8];
        v[0] = acc[i][0] + a0.x + p0.x; v[1] = acc[i][1] + a0.y + p0.y;
        v[2] = acc[i][2] + a0.z + p0.z; v[3] = acc[i][3] + a0.w + p0.w;
        v[4] = acc[i][4] + a1.x + p1.x; v[5] = acc[i][5] + a1.y + p1.y;
        v[6] = acc[i][6] + a1.z + p1.z; v[7] = acc[i][7] + a1.w + p1.w;
        float4 o0 = {v[0], v[1], v[2], v[3]};
        float4 o1 = {v[4], v[5], v[6], v[7]};
        *(float4*)&g_gated[(size_t)gr * C2 + cbase]     = o0;
        *(float4*)&g_gated[(size_t)gr * C2 + cbase + 4] = o1;
#pragma unroll
        for (int j = 0; j < 8; j++) { csum[j] += v[j]; csq[j] += v[j] * v[j]; }
    }
    const unsigned lane = tid & 31;
    const int w = tid >> 5;
#pragma unroll
    for (int j = 0; j < 8; j++) {
        csum[j] += __shfl_down_sync(0xffffffffu, csum[j], 16);
        csq[j]  += __shfl_down_sync(0xffffffffu, csq[j], 16);
    }
    if (lane < 16) {
#pragma unroll
        for (int j = 0; j < 8; j++) bred[w][lane * 8 + j] = csum[j];
    }
    __syncthreads();
    if (tid < 128) {
        double t = 0.0;
#pragma unroll
        for (int ww = 0; ww < 8; ww++) t += (double)bred[ww][tid];
        atomicAdd(&g_stats[tid], t);
    }
    __syncthreads();
    if (lane < 16) {
#pragma unroll
        for (int j = 0; j < 8; j++) bred[w][lane * 8 + j] = csq[j];
    }
    __syncthreads();
    if (tid < 128) {
        double t = 0.0;
#pragma unroll
        for (int ww = 0; ww < 8; ww++) t += (double)bred[ww][tid];
        atomicAdd(&g_stats[128 + tid], t);
    }
}

// ------------------------- finalize BN1 -------------------------
__global__ void finbn1_kernel(const float* __restrict__ g1,
                              const float* __restrict__ be1, int l) {
    int c = threadIdx.x;   // 128 threads
    double inv  = 1.0 / (double)NMROWS;
    double mean = g_stats[c] * inv;
    double var  = g_stats[128 + c] * inv - mean * mean;
    float sc = g1[l * C2 + c] * rsqrtf((float)var + EPSBN);
    g_scale1[c] = sc;
    g_shift1[c] = be1[l * C2 + c] - (float)mean * sc;
}

// ------------------------- sigmoid*softplus message sum + BN2 stats -------------------
__global__ void convreduce_kernel() {
    const int tid = threadIdx.x;
    const int w = tid >> 5;
    const unsigned lane = tid & 31;
    const int c0 = lane, c1 = lane + 32;
    const float sf0 = g_scale1[c0],      hf0 = g_shift1[c0];
    const float sf1 = g_scale1[c1],      hf1 = g_shift1[c1];
    const float sc0 = g_scale1[c0 + 64], hc0 = g_shift1[c0 + 64];
    const float sc1 = g_scale1[c1 + 64], hc1 = g_shift1[c1 + 64];
    float wsum0 = 0.f, wsum1 = 0.f, wsq0 = 0.f, wsq1 = 0.f;
    const int abase = blockIdx.x * 32 + w * 4;
    for (int a0 = 0; a0 < 4; a0++) {
        int a = abase + a0;
        const float* gp = g_gated + (size_t)a * MNBR * C2;
        float s0 = 0.f, s1 = 0.f;
#pragma unroll
        for (int m = 0; m < MNBR; m++) {
            float gf0 = gp[m * C2 + c0] * sf0 + hf0;
            float gf1 = gp[m * C2 + c1] * sf1 + hf1;
            float gc0 = gp[m * C2 + c0 + 64] * sc0 + hc0;
            float gc1 = gp[m * C2 + c1 + 64] * sc1 + hc1;
            s0 += sigmoidf_(gf0) * softplusf_(gc0);
            s1 += sigmoidf_(gf1) * softplusf_(gc1);
        }
        g_s[(size_t)a * 64 + c0] = s0;
        g_s[(size_t)a * 64 + c1] = s1;
        wsum0 += s0; wsum1 += s1;
        wsq0 += s0 * s0; wsq1 += s1 * s1;
    }
    __shared__ float bred[8][64];
    bred[w][lane]      = wsum0;
    bred[w][lane + 32] = wsum1;
    __syncthreads();
    if (tid < 64) {
        double t = 0.0;
#pragma unroll
        for (int ww = 0; ww < 8; ww++) t += (double)bred[ww][tid];
        atomicAdd(&g_stats[256 + tid], t);
    }
    __syncthreads();
    bred[w][lane]      = wsq0;
    bred[w][lane + 32] = wsq1;
    __syncthreads();
    if (tid < 64) {
        double t = 0.0;
#pragma unroll
        for (int ww = 0; ww < 8; ww++) t += (double)bred[ww][tid];
        atomicAdd(&g_stats[320 + tid], t);
    }
}

// ------------------------- finalize BN2 -------------------------
__global__ void finbn2_kernel(const float* __restrict__ g2,
                              const float* __restrict__ be2, int l) {
    int c = threadIdx.x;   // 64 threads
    double inv  = 1.0 / (double)NATOM;
    double mean = g_stats[256 + c] * inv;
    double var  = g_stats[320 + c] * inv - mean * mean;
    float sc = g2[l * AF + c] * rsqrtf((float)var + EPSBN);
    g_scale2[c] = sc;
    g_shift2[c] = be2[l * AF + c] - (float)mean * sc;
}

// ------------------------- residual + softplus -------------------------
__global__ void residual_kernel() {
    int i = blockIdx.x * 256 + threadIdx.x;    // N*AF threads
    int c = i & 63;
    float v = g_x[i] + g_s[i] * g_scale2[c] + g_shift2[c];
    g_x[i] = softplusf_(v);
}

// ------------------------- pooling -------------------------
__global__ void zpool_kernel() {
    int i = blockIdx.x * 256 + threadIdx.x;
    if (i < NSEG * AF) g_pool[i] = 0.f;
    if (i < NSEG) g_cnt[i] = 0.f;
}

__global__ void pool_kernel(const int* __restrict__ cai) {
    int i = blockIdx.x * 256 + threadIdx.x;    // N*AF threads
    int n = i >> 6, c = i & 63;
    int seg = cai[n];
    atomicAdd(&g_pool[seg * 64 + c], g_x[i]);
    if (c == 0) atomicAdd(&g_cnt[seg], 1.0f);
}

// ------------------------- head: crys_fea + 2 MLP heads -------------------------
__global__ void head_kernel(const float* __restrict__ W1, const float* __restrict__ b1,
                            const float* __restrict__ W2, const float* __restrict__ b2,
                            float* __restrict__ out) {
    __shared__ float sa[64];
    __shared__ float rw[4];
    const int b = blockIdx.x, t = threadIdx.x;   // 128 threads
    if (t < 64) {
        float cnt  = g_cnt[b];
        float crys = g_pool[b * 64 + t] / fmaxf(cnt, 1.0f);
        out[NSEG * 2 + b * 64 + t] = crys;       // crys_fea output after (N0,P) block
        sa[t] = softplusf_(crys);
    }
    __syncthreads();
    for (int p = 0; p < 2; p++) {
        float acc = b1[p * 128 + t];
#pragma unroll
        for (int f = 0; f < 64; f++) acc += sa[f] * W1[(p * 64 + f) * 128 + t];
        float pv = softplusf_(acc) * W2[p * 128 + t];
#pragma unroll
        for (int off = 16; off > 0; off >>= 1)
            pv += __shfl_down_sync(0xffffffffu, pv, off);
        if ((t & 31) == 0) rw[t >> 5] = pv;
        __syncthreads();
        if (t == 0) out[b * 2 + p] = rw[0] + rw[1] + rw[2] + rw[3] + b2[p];
        __syncthreads();
    }
}

// ------------------------- launch -------------------------
extern "C" void kernel_launch(void* const* d_in, const int* in_sizes, int n_in,
                              void* d_out, int out_size) {
    const float* atom_fea = (const float*)d_in[0];
    const float* nbr_fea  = (const float*)d_in[1];
    const float* W_embed  = (const float*)d_in[2];
    const float* b_embed  = (const float*)d_in[3];
    const float* conv_W   = (const float*)d_in[4];
    const float* conv_b   = (const float*)d_in[5];
    const float* conv_g1  = (const float*)d_in[6];
    const float* conv_be1 = (const float*)d_in[7];
    const float* conv_g2  = (const float*)d_in[8];
    const float* conv_be2 = (const float*)d_in[9];
    const float* head_W1  = (const float*)d_in[10];
    const float* head_b1  = (const float*)d_in[11];
    const float* head_W2  = (const float*)d_in[12];
    const float* head_b2  = (const float*)d_in[13];
    const int*   nbr_idx  = (const int*)d_in[14];
    const int*   cai      = (const int*)d_in[15];
    float* out = (float*)d_out;

    embed_kernel<<<NATOM / 128, 256>>>(atom_fea, W_embed, b_embed);
    for (int l = 0; l < NCONVL; l++) {
        selfnbr_kernel<<<dim3(NATOM / 128, 2), 256>>>(conv_W, conv_b, l);
        zstats_kernel<<<1, 384>>>();
        convmain_kernel<<<NMROWS / 128, 256>>>(nbr_fea, nbr_idx, conv_W, l);
        finbn1_kernel<<<1, 128>>>(conv_g1, conv_be1, l);
        convreduce_kernel<<<NATOM / 32, 256>>>();
        finbn2_kernel<<<1, 64>>>(conv_g2, conv_be2, l);
        residual_kernel<<<NATOM * AF / 256, 256>>>();
    }
    zpool_kernel<<<(NSEG * AF + NSEG + 255) / 256, 256>>>();
    pool_kernel<<<NATOM * AF / 256, 256>>>(cai);
    head_kernel<<<NSEG, 128>>>(head_W1, head_b1, head_W2, head_b2, out);
}

// round 5
// speedup vs baseline: 1.2549x; 1.2549x over previous
#include <cuda_runtime.h>
#include <cuda_fp16.h>

#define NATOM 131072
#define MNBR  12
#define ORIGF 92
#define NBRF  41
#define AF    64
#define C2    128      // 2*AF
#define FIN   169      // 2*AF + NBRF
#define NSEG  1024
#define NCONVL 3
#define NMROWS (NATOM*MNBR)   // 1572864
#define EPSBN 1e-5f

#define BR 96          // conv block rows (= 8 atoms * 12 nbrs)
#define CTH 192        // conv threads

// ------------------------- static device scratch -------------------------
__device__ float  g_x[NATOM*AF];                    // current atom features
__device__ float  g_A1[NATOM*C2];                   // self contribution + bias (fp32)
__device__ __half g_P_h[NATOM*C2];                  // neighbor contribution (fp16, 33MB -> L2 resident)
__device__ __half g_gated_h[(size_t)NMROWS*C2];     // pre-BN conv output (fp16, 402MB)
__device__ float  g_s[NATOM*AF];                    // summed messages
__device__ double g_stats[384];                     // [0:128) sum1, [128:256) sq1, [256:320) sum2, [320:384) sq2
__device__ float  g_scale1[C2], g_shift1[C2];
__device__ float  g_scale2[AF], g_shift2[AF];
__device__ float  g_pool[NSEG*AF];
__device__ float  g_cnt[NSEG];

// ------------------------- math helpers -------------------------
__device__ __forceinline__ float softplusf_(float x) {
    // log1p(e^x) = max(x,0) + log1p(e^-|x|), branchless fast-math
    return fmaxf(x, 0.0f) + __logf(1.0f + __expf(-fabsf(x)));
}
__device__ __forceinline__ float sigmoidf_(float x) {
    return __fdividef(1.0f, 1.0f + __expf(-x));
}

// ------------------------- embed: g_x = atom_fea @ W_embed + b -------------------------
__global__ void embed_kernel(const float* __restrict__ A,
                             const float* __restrict__ W,
                             const float* __restrict__ b) {
    __shared__ float As[128][96];
    __shared__ float Ws[92][64];
    const int tid  = threadIdx.x;
    const int row0 = blockIdx.x * 128;
    for (int i = tid; i < 128 * 92; i += 256) {
        int r = i / 92, k = i - r * 92;
        As[r][k] = A[(size_t)(row0 + r) * 92 + k];
    }
    for (int i = tid; i < 92 * 64; i += 256) Ws[i >> 6][i & 63] = W[i];
    __syncthreads();
    const int ty = tid >> 4, tx = tid & 15;
    float acc[8][4];
#pragma unroll
    for (int i = 0; i < 8; i++) { acc[i][0]=0.f; acc[i][1]=0.f; acc[i][2]=0.f; acc[i][3]=0.f; }
    for (int k = 0; k < 92; k++) {
        float av[8];
#pragma unroll
        for (int i = 0; i < 8; i++) av[i] = As[ty * 8 + i][k];
        float4 bv = *(const float4*)&Ws[k][tx * 4];
#pragma unroll
        for (int i = 0; i < 8; i++) {
            acc[i][0] += av[i] * bv.x; acc[i][1] += av[i] * bv.y;
            acc[i][2] += av[i] * bv.z; acc[i][3] += av[i] * bv.w;
        }
    }
    float4 bb = *(const float4*)&b[tx * 4];
#pragma unroll
    for (int i = 0; i < 8; i++) {
        float4 o;
        o.x = acc[i][0] + bb.x; o.y = acc[i][1] + bb.y;
        o.z = acc[i][2] + bb.z; o.w = acc[i][3] + bb.w;
        *(float4*)&g_x[(size_t)(row0 + ty * 8 + i) * 64 + tx * 4] = o;
    }
}

// ------------------------- self/nbr GEMMs: A1 = X@W[0:64]+b (fp32); P = X@W[64:128] (fp16)
__global__ void selfnbr_kernel(const float* __restrict__ convW,
                               const float* __restrict__ convb, int l) {
    __shared__ float Xs[128][68];
    __shared__ float Ws[64][128];
    const int tid  = threadIdx.x;
    const int row0 = blockIdx.x * 128;
    const int half = blockIdx.y;   // 0: self -> g_A1(+bias), 1: nbr -> g_P_h
    const float* W = convW + ((size_t)l * FIN + half * 64) * C2;
    for (int i = tid; i < 128 * 64; i += 256) {
        int r = i >> 6, k = i & 63;
        Xs[r][k] = g_x[(size_t)(row0 + r) * 64 + k];
    }
    for (int i = tid; i < 64 * 128; i += 256) Ws[i >> 7][i & 127] = W[i];
    __syncthreads();
    const int ty = tid >> 4, tx = tid & 15;
    float acc[8][8];
#pragma unroll
    for (int i = 0; i < 8; i++)
#pragma unroll
        for (int j = 0; j < 8; j++) acc[i][j] = 0.f;
    for (int k = 0; k < 64; k++) {
        float av[8];
#pragma unroll
        for (int i = 0; i < 8; i++) av[i] = Xs[ty * 8 + i][k];
        float4 b0 = *(const float4*)&Ws[k][tx * 8];
        float4 b1 = *(const float4*)&Ws[k][tx * 8 + 4];
#pragma unroll
        for (int i = 0; i < 8; i++) {
            acc[i][0] += av[i] * b0.x; acc[i][1] += av[i] * b0.y;
            acc[i][2] += av[i] * b0.z; acc[i][3] += av[i] * b0.w;
            acc[i][4] += av[i] * b1.x; acc[i][5] += av[i] * b1.y;
            acc[i][6] += av[i] * b1.z; acc[i][7] += av[i] * b1.w;
        }
    }
    if (!half) {
        float4 c0 = *(const float4*)&convb[l * C2 + tx * 8];
        float4 c1 = *(const float4*)&convb[l * C2 + tx * 8 + 4];
#pragma unroll
        for (int i = 0; i < 8; i++) {
            size_t base = (size_t)(row0 + ty * 8 + i) * C2 + tx * 8;
            float4 o0, o1;
            o0.x = acc[i][0] + c0.x; o0.y = acc[i][1] + c0.y;
            o0.z = acc[i][2] + c0.z; o0.w = acc[i][3] + c0.w;
            o1.x = acc[i][4] + c1.x; o1.y = acc[i][5] + c1.y;
            o1.z = acc[i][6] + c1.z; o1.w = acc[i][7] + c1.w;
            *(float4*)&g_A1[base]     = o0;
            *(float4*)&g_A1[base + 4] = o1;
        }
    } else {
#pragma unroll
        for (int i = 0; i < 8; i++) {
            size_t base = (size_t)(row0 + ty * 8 + i) * C2 + tx * 8;
            __half2 hv[4];
            hv[0] = __floats2half2_rn(acc[i][0], acc[i][1]);
            hv[1] = __floats2half2_rn(acc[i][2], acc[i][3]);
            hv[2] = __floats2half2_rn(acc[i][4], acc[i][5]);
            hv[3] = __floats2half2_rn(acc[i][6], acc[i][7]);
            *(uint4*)&g_P_h[base] = *(uint4*)hv;
        }
    }
}

// ------------------------- zero stats -------------------------
__global__ void zstats_kernel() {
    if (threadIdx.x < 384) g_stats[threadIdx.x] = 0.0;
}

// dynamic smem layout for convmain (bytes):
#define SM_ES   0                      // float [96][44]  = 16896
#define SM_WS   16896                  // float [41][128] = 20992
#define SM_PS   37888                  // half  [96][128] = 24576
#define SM_AS   62464                  // float [8][128]  = 4096
#define SM_IDX  66560                  // int   [96]      = 384
#define SM_BRED 66944                  // float [6][128]  = 3072
#define SM_TOTAL 70016

// ------------------------- main conv: gated = edge@We + A1[n] + P[idx] ; BN1 stats ----
__global__ void __launch_bounds__(CTH, 3)
convmain_kernel(const float* __restrict__ nbr_fea,
                const int* __restrict__ nbr_idx,
                const float* __restrict__ convW, int l) {
    extern __shared__ char sm[];
    float*  Es    = (float*)(sm + SM_ES);
    float*  Ws    = (float*)(sm + SM_WS);
    __half* Ps    = (__half*)(sm + SM_PS);
    float*  As    = (float*)(sm + SM_AS);
    int*    s_idx = (int*)(sm + SM_IDX);
    float*  bred  = (float*)(sm + SM_BRED);

    const int tid = threadIdx.x;
    const int r0  = blockIdx.x * BR;
    const int n0  = blockIdx.x * 8;

    if (tid < BR) s_idx[tid] = nbr_idx[r0 + tid];
    __syncthreads();

    // ---- async gather of P rows (fp16, 256B/row, 16 chunks) -> overlapped with GEMM
#pragma unroll
    for (int i = 0; i < 8; i++) {
        int c = i * CTH + tid;              // 0..1535
        int r = c >> 4, off = (c & 15) * 8; // half elements
        const __half* src = g_P_h + (size_t)s_idx[r] * C2 + off;
        unsigned sdst = (unsigned)__cvta_generic_to_shared(Ps + r * C2 + off);
        asm volatile("cp.async.cg.shared.global [%0], [%1], 16;" :: "r"(sdst), "l"(src));
    }
    // ---- async load of the 8 A1 rows for this block
#pragma unroll
    for (int i = 0; i < 2; i++) {
        int c = i * CTH + tid;
        if (c < 256) {
            int r = c >> 5, off = (c & 31) * 4;
            const float* src = g_A1 + (size_t)(n0 + r) * C2 + off;
            unsigned sdst = (unsigned)__cvta_generic_to_shared(As + r * C2 + off);
            asm volatile("cp.async.cg.shared.global [%0], [%1], 16;" :: "r"(sdst), "l"(src));
        }
    }
    asm volatile("cp.async.commit_group;");

    // ---- stage edge features + weights
    const float* Eg = nbr_fea + (size_t)r0 * NBRF;
    for (int i = tid; i < BR * NBRF; i += CTH) {
        int r = i / NBRF, k = i - r * NBRF;
        Es[r * 44 + k] = Eg[i];
    }
    const float* We = convW + ((size_t)l * FIN + 128) * C2;
    for (int i = tid; i < NBRF * C2; i += CTH) Ws[i] = We[i];
    __syncthreads();

    const int ty = tid >> 4, tx = tid & 15;   // ty 0..11, tx 0..15
    float acc[8][8];
#pragma unroll
    for (int i = 0; i < 8; i++)
#pragma unroll
        for (int j = 0; j < 8; j++) acc[i][j] = 0.f;
    for (int k = 0; k < NBRF; k++) {
        float av[8];
#pragma unroll
        for (int i = 0; i < 8; i++) av[i] = Es[(ty * 8 + i) * 44 + k];
        float4 b0 = *(const float4*)&Ws[k * C2 + tx * 8];
        float4 b1 = *(const float4*)&Ws[k * C2 + tx * 8 + 4];
#pragma unroll
        for (int i = 0; i < 8; i++) {
            acc[i][0] += av[i] * b0.x; acc[i][1] += av[i] * b0.y;
            acc[i][2] += av[i] * b0.z; acc[i][3] += av[i] * b0.w;
            acc[i][4] += av[i] * b1.x; acc[i][5] += av[i] * b1.y;
            acc[i][6] += av[i] * b1.z; acc[i][7] += av[i] * b1.w;
        }
    }
    asm volatile("cp.async.wait_group 0;" ::: "memory");
    __syncthreads();

    // ---- epilogue: add gathered per-atom terms, store fp16 gated, BN1 stats
    float csum[8], csq[8];
#pragma unroll
    for (int j = 0; j < 8; j++) { csum[j] = 0.f; csq[j] = 0.f; }
    const int cbase = tx * 8;
#pragma unroll
    for (int i = 0; i < 8; i++) {
        int r  = ty * 8 + i;
        int gr = r0 + r;
        const float* arow = As + (r / MNBR) * C2;
        float4 a0 = *(const float4*)&arow[cbase];
        float4 a1 = *(const float4*)&arow[cbase + 4];
        __half2 ph[4];
        *(uint4*)ph = *(const uint4*)(Ps + r * C2 + cbase);
        float2 p0 = __half22float2(ph[0]);
        float2 p1 = __half22float2(ph[1]);
        float2 p2 = __half22float2(ph[2]);
        float2 p3 = __half22float2(ph[3]);
        float v[8];
        v[0] = acc[i][0] + a0.x + p0.x; v[1] = acc[i][1] + a0.y + p0.y;
        v[2] = acc[i][2] + a0.z + p1.x; v[3] = acc[i][3] + a0.w + p1.y;
        v[4] = acc[i][4] + a1.x + p2.x; v[5] = acc[i][5] + a1.y + p2.y;
        v[6] = acc[i][6] + a1.z + p3.x; v[7] = acc[i][7] + a1.w + p3.y;
        __half2 hv[4];
        hv[0] = __floats2half2_rn(v[0], v[1]);
        hv[1] = __floats2half2_rn(v[2], v[3]);
        hv[2] = __floats2half2_rn(v[4], v[5]);
        hv[3] = __floats2half2_rn(v[6], v[7]);
        *(uint4*)&g_gated_h[(size_t)gr * C2 + cbase] = *(uint4*)hv;
#pragma unroll
        for (int j = 0; j < 8; j++) { csum[j] += v[j]; csq[j] += v[j] * v[j]; }
    }
    const unsigned lane = tid & 31;
    const int w = tid >> 5;   // 0..5
#pragma unroll
    for (int j = 0; j < 8; j++) {
        csum[j] += __shfl_down_sync(0xffffffffu, csum[j], 16);
        csq[j]  += __shfl_down_sync(0xffffffffu, csq[j], 16);
    }
    if (lane < 16) {
#pragma unroll
        for (int j = 0; j < 8; j++) bred[w * C2 + lane * 8 + j] = csum[j];
    }
    __syncthreads();
    if (tid < 128) {
        double t = 0.0;
#pragma unroll
        for (int ww = 0; ww < 6; ww++) t += (double)bred[ww * C2 + tid];
        atomicAdd(&g_stats[tid], t);
    }
    __syncthreads();
    if (lane < 16) {
#pragma unroll
        for (int j = 0; j < 8; j++) bred[w * C2 + lane * 8 + j] = csq[j];
    }
    __syncthreads();
    if (tid < 128) {
        double t = 0.0;
#pragma unroll
        for (int ww = 0; ww < 6; ww++) t += (double)bred[ww * C2 + tid];
        atomicAdd(&g_stats[128 + tid], t);
    }
}

// ------------------------- finalize BN1 -------------------------
__global__ void finbn1_kernel(const float* __restrict__ g1,
                              const float* __restrict__ be1, int l) {
    int c = threadIdx.x;   // 128 threads
    double inv  = 1.0 / (double)NMROWS;
    double mean = g_stats[c] * inv;
    double var  = g_stats[128 + c] * inv - mean * mean;
    float sc = g1[l * C2 + c] * rsqrtf((float)var + EPSBN);
    g_scale1[c] = sc;
    g_shift1[c] = be1[l * C2 + c] - (float)mean * sc;
}

// ------------------------- sigmoid*softplus message sum + BN2 stats -------------------
__global__ void convreduce_kernel() {
    const int tid = threadIdx.x;          // 256
    const int w = tid >> 5;               // 0..7
    const unsigned lane = tid & 31;
    // lane handles channel pair (2*lane, 2*lane+1) for both filter and core halves
    const float2 sf = *(const float2*)&g_scale1[2 * lane];
    const float2 hf = *(const float2*)&g_shift1[2 * lane];
    const float2 sc = *(const float2*)&g_scale1[64 + 2 * lane];
    const float2 hc = *(const float2*)&g_shift1[64 + 2 * lane];
    const __half2* G = (const __half2*)g_gated_h;   // rows of 64 half2
    float wsum0 = 0.f, wsum1 = 0.f, wsq0 = 0.f, wsq1 = 0.f;
    const int abase = blockIdx.x * 32 + w * 4;
    for (int a0 = 0; a0 < 4; a0++) {
        int a = abase + a0;
        size_t base = (size_t)a * MNBR * 64;
        float s0 = 0.f, s1 = 0.f;
#pragma unroll
        for (int m = 0; m < MNBR; m++) {
            float2 f = __half22float2(G[base + m * 64 + lane]);
            float2 c = __half22float2(G[base + m * 64 + 32 + lane]);
            float gf0 = f.x * sf.x + hf.x;
            float gf1 = f.y * sf.y + hf.y;
            float gc0 = c.x * sc.x + hc.x;
            float gc1 = c.y * sc.y + hc.y;
            s0 += sigmoidf_(gf0) * softplusf_(gc0);
            s1 += sigmoidf_(gf1) * softplusf_(gc1);
        }
        float2 so = {s0, s1};
        *(float2*)&g_s[(size_t)a * 64 + 2 * lane] = so;
        wsum0 += s0; wsum1 += s1;
        wsq0 += s0 * s0; wsq1 += s1 * s1;
    }
    __shared__ float bred[8][64];
    bred[w][2 * lane]     = wsum0;
    bred[w][2 * lane + 1] = wsum1;
    __syncthreads();
    if (tid < 64) {
        double t = 0.0;
#pragma unroll
        for (int ww = 0; ww < 8; ww++) t += (double)bred[ww][tid];
        atomicAdd(&g_stats[256 + tid], t);
    }
    __syncthreads();
    bred[w][2 * lane]     = wsq0;
    bred[w][2 * lane + 1] = wsq1;
    __syncthreads();
    if (tid < 64) {
        double t = 0.0;
#pragma unroll
        for (int ww = 0; ww < 8; ww++) t += (double)bred[ww][tid];
        atomicAdd(&g_stats[320 + tid], t);
    }
}

// ------------------------- finalize BN2 -------------------------
__global__ void finbn2_kernel(const float* __restrict__ g2,
                              const float* __restrict__ be2, int l) {
    int c = threadIdx.x;   // 64 threads
    double inv  = 1.0 / (double)NATOM;
    double mean = g_stats[256 + c] * inv;
    double var  = g_stats[320 + c] * inv - mean * mean;
    float sc = g2[l * AF + c] * rsqrtf((float)var + EPSBN);
    g_scale2[c] = sc;
    g_shift2[c] = be2[l * AF + c] - (float)mean * sc;
}

// ------------------------- residual + softplus -------------------------
__global__ void residual_kernel() {
    int i = blockIdx.x * 256 + threadIdx.x;    // N*AF threads
    int c = i & 63;
    float v = g_x[i] + g_s[i] * g_scale2[c] + g_shift2[c];
    g_x[i] = softplusf_(v);
}

// ------------------------- pooling -------------------------
__global__ void zpool_kernel() {
    int i = blockIdx.x * 256 + threadIdx.x;
    if (i < NSEG * AF) g_pool[i] = 0.f;
    if (i < NSEG) g_cnt[i] = 0.f;
}

__global__ void pool_kernel(const int* __restrict__ cai) {
    int i = blockIdx.x * 256 + threadIdx.x;    // N*AF threads
    int n = i >> 6, c = i & 63;
    int seg = cai[n];
    atomicAdd(&g_pool[seg * 64 + c], g_x[i]);
    if (c == 0) atomicAdd(&g_cnt[seg], 1.0f);
}

// ------------------------- head: crys_fea + 2 MLP heads -------------------------
__global__ void head_kernel(const float* __restrict__ W1, const float* __restrict__ b1,
                            const float* __restrict__ W2, const float* __restrict__ b2,
                            float* __restrict__ out) {
    __shared__ float sa[64];
    __shared__ float rw[4];
    const int b = blockIdx.x, t = threadIdx.x;   // 128 threads
    if (t < 64) {
        float cnt  = g_cnt[b];
        float crys = g_pool[b * 64 + t] / fmaxf(cnt, 1.0f);
        out[NSEG * 2 + b * 64 + t] = crys;       // crys_fea output after (N0,P) block
        sa[t] = softplusf_(crys);
    }
    __syncthreads();
    for (int p = 0; p < 2; p++) {
        float acc = b1[p * 128 + t];
#pragma unroll
        for (int f = 0; f < 64; f++) acc += sa[f] * W1[(p * 64 + f) * 128 + t];
        float pv = softplusf_(acc) * W2[p * 128 + t];
#pragma unroll
        for (int off = 16; off > 0; off >>= 1)
            pv += __shfl_down_sync(0xffffffffu, pv, off);
        if ((t & 31) == 0) rw[t >> 5] = pv;
        __syncthreads();
        if (t == 0) out[b * 2 + p] = rw[0] + rw[1] + rw[2] + rw[3] + b2[p];
        __syncthreads();
    }
}

// ------------------------- launch -------------------------
extern "C" void kernel_launch(void* const* d_in, const int* in_sizes, int n_in,
                              void* d_out, int out_size) {
    const float* atom_fea = (const float*)d_in[0];
    const float* nbr_fea  = (const float*)d_in[1];
    const float* W_embed  = (const float*)d_in[2];
    const float* b_embed  = (const float*)d_in[3];
    const float* conv_W   = (const float*)d_in[4];
    const float* conv_b   = (const float*)d_in[5];
    const float* conv_g1  = (const float*)d_in[6];
    const float* conv_be1 = (const float*)d_in[7];
    const float* conv_g2  = (const float*)d_in[8];
    const float* conv_be2 = (const float*)d_in[9];
    const float* head_W1  = (const float*)d_in[10];
    const float* head_b1  = (const float*)d_in[11];
    const float* head_W2  = (const float*)d_in[12];
    const float* head_b2  = (const float*)d_in[13];
    const int*   nbr_idx  = (const int*)d_in[14];
    const int*   cai      = (const int*)d_in[15];
    float* out = (float*)d_out;

    cudaFuncSetAttribute(convmain_kernel,
                         cudaFuncAttributeMaxDynamicSharedMemorySize, SM_TOTAL);

    embed_kernel<<<NATOM / 128, 256>>>(atom_fea, W_embed, b_embed);
    for (int l = 0; l < NCONVL; l++) {
        selfnbr_kernel<<<dim3(NATOM / 128, 2), 256>>>(conv_W, conv_b, l);
        zstats_kernel<<<1, 384>>>();
        convmain_kernel<<<NMROWS / BR, CTH, SM_TOTAL>>>(nbr_fea, nbr_idx, conv_W, l);
        finbn1_kernel<<<1, 128>>>(conv_g1, conv_be1, l);
        convreduce_kernel<<<NATOM / 32, 256>>>();
        finbn2_kernel<<<1, 64>>>(conv_g2, conv_be2, l);
        residual_kernel<<<NATOM * AF / 256, 256>>>();
    }
    zpool_kernel<<<(NSEG * AF + NSEG + 255) / 256, 256>>>();
    pool_kernel<<<NATOM * AF / 256, 256>>>(cai);
    head_kernel<<<NSEG, 128>>>(head_W1, head_b1, head_W2, head_b2, out);
}

// round 6
// speedup vs baseline: 1.4551x; 1.1596x over previous
#include <cuda_runtime.h>
#include <cuda_fp16.h>

#define NATOM 131072
#define MNBR  12
#define ORIGF 92
#define NBRF  41
#define AF    64
#define C2    128      // 2*AF
#define FIN   169      // 2*AF + NBRF
#define NSEG  1024
#define NCONVL 3
#define NMROWS (NATOM*MNBR)   // 1572864
#define EPSBN 1e-5f

// ------------------------- static device scratch -------------------------
__device__ float  g_x[NATOM*AF];                    // current atom features
__device__ float  g_A1[NATOM*C2];                   // self contribution + bias (fp32)
__device__ __half g_P_h[NATOM*C2];                  // neighbor contribution (fp16, 33MB, L2 resident)
__device__ __half g_gated_h[(size_t)NMROWS*C2];     // pre-BN conv output (fp16, 402MB)
__device__ float  g_s[NATOM*AF];                    // summed messages
__device__ double g_stats[384];                     // [0:128) sum1, [128:256) sq1, [256:320) sum2, [320:384) sq2
__device__ float  g_scale1[C2], g_shift1[C2];
__device__ float  g_scale2[AF], g_shift2[AF];
__device__ float  g_pool[NSEG*AF];
__device__ float  g_cnt[NSEG];

// ------------------------- math helpers -------------------------
__device__ __forceinline__ float softplusf_(float x) {
    return fmaxf(x, 0.0f) + __logf(1.0f + __expf(-fabsf(x)));
}
__device__ __forceinline__ float sigmoidf_(float x) {
    return __fdividef(1.0f, 1.0f + __expf(-x));
}
__device__ __forceinline__ unsigned tf32_(float x) {
    unsigned y;
    asm("cvt.rna.tf32.f32 %0, %1;" : "=r"(y) : "f"(x));
    return y;
}

#define MMA_TF32(C, A, B) \
  asm volatile("mma.sync.aligned.m16n8k8.row.col.f32.tf32.tf32.f32 " \
    "{%0,%1,%2,%3}, {%4,%5,%6,%7}, {%8,%9}, {%0,%1,%2,%3};" \
    : "+f"((C)[0]), "+f"((C)[1]), "+f"((C)[2]), "+f"((C)[3]) \
    : "r"((A)[0]), "r"((A)[1]), "r"((A)[2]), "r"((A)[3]), \
      "r"((B)[0]), "r"((B)[1]))

// ------------------------- embed: g_x = atom_fea @ W_embed + b -------------------------
__global__ void embed_kernel(const float* __restrict__ A,
                             const float* __restrict__ W,
                             const float* __restrict__ b) {
    __shared__ float As[128][96];
    __shared__ float Ws[92][64];
    const int tid  = threadIdx.x;
    const int row0 = blockIdx.x * 128;
    for (int i = tid; i < 128 * 92; i += 256) {
        int r = i / 92, k = i - r * 92;
        As[r][k] = A[(size_t)(row0 + r) * 92 + k];
    }
    for (int i = tid; i < 92 * 64; i += 256) Ws[i >> 6][i & 63] = W[i];
    __syncthreads();
    const int ty = tid >> 4, tx = tid & 15;
    float acc[8][4];
#pragma unroll
    for (int i = 0; i < 8; i++) { acc[i][0]=0.f; acc[i][1]=0.f; acc[i][2]=0.f; acc[i][3]=0.f; }
    for (int k = 0; k < 92; k++) {
        float av[8];
#pragma unroll
        for (int i = 0; i < 8; i++) av[i] = As[ty * 8 + i][k];
        float4 bv = *(const float4*)&Ws[k][tx * 4];
#pragma unroll
        for (int i = 0; i < 8; i++) {
            acc[i][0] += av[i] * bv.x; acc[i][1] += av[i] * bv.y;
            acc[i][2] += av[i] * bv.z; acc[i][3] += av[i] * bv.w;
        }
    }
    float4 bb = *(const float4*)&b[tx * 4];
#pragma unroll
    for (int i = 0; i < 8; i++) {
        float4 o;
        o.x = acc[i][0] + bb.x; o.y = acc[i][1] + bb.y;
        o.z = acc[i][2] + bb.z; o.w = acc[i][3] + bb.w;
        *(float4*)&g_x[(size_t)(row0 + ty * 8 + i) * 64 + tx * 4] = o;
    }
}

// ------------------------- self/nbr GEMMs (tf32 tensor cores) -------------------------
// A1 = X@W[0:64]+b (fp32) ; P = X@W[64:128] (fp16)
#define SN_XS 0              // u32 [128][68] = 34816
#define SN_WS 34816          // u32 [64][136] = 34816
#define SN_TOTAL 69632

__global__ void __launch_bounds__(256, 2)
selfnbr_kernel(const float* __restrict__ convW,
               const float* __restrict__ convb, int l) {
    extern __shared__ char sm[];
    unsigned* Xs = (unsigned*)(sm + SN_XS);
    unsigned* Ws = (unsigned*)(sm + SN_WS);
    const int tid  = threadIdx.x;
    const int row0 = blockIdx.x * 128;
    const int half = blockIdx.y;
    const float* W = convW + ((size_t)l * FIN + half * 64) * C2;
    for (int i = tid; i < 128 * 64; i += 256) {
        int r = i >> 6, k = i & 63;
        Xs[r * 68 + k] = tf32_(g_x[(size_t)(row0 + r) * 64 + k]);
    }
    for (int i = tid; i < 64 * 128; i += 256) {
        int k = i >> 7, n = i & 127;
        Ws[k * 136 + n] = tf32_(W[i]);
    }
    __syncthreads();

    const int lane = tid & 31, w = tid >> 5;
    const int rg = w & 3, cg = w >> 2;
    const int m0 = rg * 32, n0 = cg * 64;
    const int qr = lane >> 2, qc = lane & 3;

    float c[2][8][4];
#pragma unroll
    for (int mt = 0; mt < 2; mt++)
#pragma unroll
        for (int nt = 0; nt < 8; nt++)
#pragma unroll
            for (int j = 0; j < 4; j++) c[mt][nt][j] = 0.f;

#pragma unroll
    for (int ks = 0; ks < 8; ks++) {
        const int k0 = ks * 8;
        unsigned a[2][4];
#pragma unroll
        for (int mt = 0; mt < 2; mt++) {
            int mr = m0 + mt * 16 + qr;
            a[mt][0] = Xs[mr * 68 + k0 + qc];
            a[mt][1] = Xs[(mr + 8) * 68 + k0 + qc];
            a[mt][2] = Xs[mr * 68 + k0 + 4 + qc];
            a[mt][3] = Xs[(mr + 8) * 68 + k0 + 4 + qc];
        }
        unsigned b[8][2];
#pragma unroll
        for (int nt = 0; nt < 8; nt++) {
            int n = n0 + nt * 8 + qr;
            b[nt][0] = Ws[(k0 + qc) * 136 + n];
            b[nt][1] = Ws[(k0 + 4 + qc) * 136 + n];
        }
#pragma unroll
        for (int mt = 0; mt < 2; mt++)
#pragma unroll
            for (int nt = 0; nt < 8; nt++) MMA_TF32(c[mt][nt], a[mt], b[nt]);
    }

    if (half == 0) {
#pragma unroll
        for (int nt = 0; nt < 8; nt++) {
            int col = n0 + nt * 8 + 2 * qc;
            float2 bias = *(const float2*)&convb[l * C2 + col];
#pragma unroll
            for (int mt = 0; mt < 2; mt++) {
                int row = row0 + m0 + mt * 16 + qr;
                float2 o0 = {c[mt][nt][0] + bias.x, c[mt][nt][1] + bias.y};
                float2 o1 = {c[mt][nt][2] + bias.x, c[mt][nt][3] + bias.y};
                *(float2*)&g_A1[(size_t)row * C2 + col]       = o0;
                *(float2*)&g_A1[(size_t)(row + 8) * C2 + col] = o1;
            }
        }
    } else {
#pragma unroll
        for (int nt = 0; nt < 8; nt++) {
            int col = n0 + nt * 8 + 2 * qc;
#pragma unroll
            for (int mt = 0; mt < 2; mt++) {
                int row = row0 + m0 + mt * 16 + qr;
                *(__half2*)&g_P_h[(size_t)row * C2 + col] =
                    __floats2half2_rn(c[mt][nt][0], c[mt][nt][1]);
                *(__half2*)&g_P_h[(size_t)(row + 8) * C2 + col] =
                    __floats2half2_rn(c[mt][nt][2], c[mt][nt][3]);
            }
        }
    }
}

// ------------------------- zero stats -------------------------
__global__ void zstats_kernel() {
    if (threadIdx.x < 384) g_stats[threadIdx.x] = 0.0;
}

// ------------------------- main conv (tf32 tensor cores) -------------------------
// gated = edge@We + A1[atom] + P[idx] ; fp16 store ; BN1 stats
#define CM_ES    0            // u32 [128][52] = 26624
#define CM_WS    26624        // u32 [48][136] = 26112  (end 52736)
#define CM_STAGE 0            // float [128][72] = 36864 (reuses Es/Ws after MMA)
#define CM_IDX   52736        // int [128] = 512
#define CM_BREDS 53248        // float [8][64] = 2048
#define CM_BREDQ 55296        // float [8][64] = 2048
#define CM_TOTAL 57344

__global__ void __launch_bounds__(256, 2)
convmain_kernel(const float* __restrict__ nbr_fea,
                const int* __restrict__ nbr_idx,
                const float* __restrict__ convW, int l) {
    extern __shared__ char sm[];
    unsigned* Es    = (unsigned*)(sm + CM_ES);
    unsigned* Ws    = (unsigned*)(sm + CM_WS);
    float*    stage = (float*)(sm + CM_STAGE);
    int*      s_idx = (int*)(sm + CM_IDX);
    float*    bredS = (float*)(sm + CM_BREDS);
    float*    bredQ = (float*)(sm + CM_BREDQ);

    const int tid = threadIdx.x;
    const int r0  = blockIdx.x * 128;

    if (tid < 128) s_idx[tid] = nbr_idx[r0 + tid];

    const float* Eg = nbr_fea + (size_t)r0 * NBRF;
    for (int i = tid; i < 128 * NBRF; i += 256) {
        int r = i / NBRF, k = i - r * NBRF;
        Es[r * 52 + k] = tf32_(Eg[i]);
    }
    for (int i = tid; i < 128 * 8; i += 256) {
        int r = i >> 3, k = 41 + (i & 7);
        if (k < 48) Es[r * 52 + k] = 0u;
    }
    const float* We = convW + ((size_t)l * FIN + 128) * C2;
    for (int i = tid; i < NBRF * C2; i += 256) {
        int k = i >> 7, n = i & 127;
        Ws[k * 136 + n] = tf32_(We[i]);
    }
    for (int i = tid; i < 7 * C2; i += 256) {
        int k = 41 + (i >> 7), n = i & 127;
        Ws[k * 136 + n] = 0u;
    }
    __syncthreads();

    const int lane = tid & 31, w = tid >> 5;
    const int rg = w & 3, cg = w >> 2;
    const int m0 = rg * 32, n0 = cg * 64;
    const int qr = lane >> 2, qc = lane & 3;

    float c[2][8][4];
#pragma unroll
    for (int mt = 0; mt < 2; mt++)
#pragma unroll
        for (int nt = 0; nt < 8; nt++)
#pragma unroll
            for (int j = 0; j < 4; j++) c[mt][nt][j] = 0.f;

#pragma unroll
    for (int ks = 0; ks < 6; ks++) {
        const int k0 = ks * 8;
        unsigned a[2][4];
#pragma unroll
        for (int mt = 0; mt < 2; mt++) {
            int mr = m0 + mt * 16 + qr;
            a[mt][0] = Es[mr * 52 + k0 + qc];
            a[mt][1] = Es[(mr + 8) * 52 + k0 + qc];
            a[mt][2] = Es[mr * 52 + k0 + 4 + qc];
            a[mt][3] = Es[(mr + 8) * 52 + k0 + 4 + qc];
        }
        unsigned b[8][2];
#pragma unroll
        for (int nt = 0; nt < 8; nt++) {
            int n = n0 + nt * 8 + qr;
            b[nt][0] = Ws[(k0 + qc) * 136 + n];
            b[nt][1] = Ws[(k0 + 4 + qc) * 136 + n];
        }
#pragma unroll
        for (int mt = 0; mt < 2; mt++)
#pragma unroll
            for (int nt = 0; nt < 8; nt++) MMA_TF32(c[mt][nt], a[mt], b[nt]);
    }

    // ---- epilogue, one 64-col half at a time (stage reuses Es/Ws smem) ----
    const int c8  = tid & 7;       // 8-col chunk within half
    const int rgr = tid >> 3;      // 32 row groups of 4 rows
#pragma unroll 1
    for (int h = 0; h < 2; h++) {
        __syncthreads();
        if (cg == h) {
#pragma unroll
            for (int mt = 0; mt < 2; mt++)
#pragma unroll
                for (int nt = 0; nt < 8; nt++) {
                    int row = m0 + mt * 16 + qr;
                    int col = nt * 8 + 2 * qc;
                    float2 s0 = {c[mt][nt][0], c[mt][nt][1]};
                    float2 s1 = {c[mt][nt][2], c[mt][nt][3]};
                    *(float2*)&stage[row * 72 + col]       = s0;
                    *(float2*)&stage[(row + 8) * 72 + col] = s1;
                }
        }
        __syncthreads();

        float sum[8], sq[8];
#pragma unroll
        for (int j = 0; j < 8; j++) { sum[j] = 0.f; sq[j] = 0.f; }
#pragma unroll
        for (int rr = 0; rr < 4; rr++) {
            int row  = rgr * 4 + rr;
            int gr   = r0 + row;
            int atom = gr / MNBR;
            const float*  ap = g_A1  + (size_t)atom * C2 + h * 64 + c8 * 8;
            const __half* pp = g_P_h + (size_t)s_idx[row] * C2 + h * 64 + c8 * 8;
            float4 s0 = *(float4*)&stage[row * 72 + c8 * 8];
            float4 s1 = *(float4*)&stage[row * 72 + c8 * 8 + 4];
            float4 A0 = *(const float4*)ap;
            float4 A1v = *(const float4*)(ap + 4);
            uint4 pr = *(const uint4*)pp;
            __half2* ph = (__half2*)&pr;
            float2 p0 = __half22float2(ph[0]);
            float2 p1 = __half22float2(ph[1]);
            float2 p2 = __half22float2(ph[2]);
            float2 p3 = __half22float2(ph[3]);
            float v[8];
            v[0] = s0.x + A0.x + p0.x;  v[1] = s0.y + A0.y + p0.y;
            v[2] = s0.z + A0.z + p1.x;  v[3] = s0.w + A0.w + p1.y;
            v[4] = s1.x + A1v.x + p2.x; v[5] = s1.y + A1v.y + p2.y;
            v[6] = s1.z + A1v.z + p3.x; v[7] = s1.w + A1v.w + p3.y;
            __half2 hv[4];
            hv[0] = __floats2half2_rn(v[0], v[1]);
            hv[1] = __floats2half2_rn(v[2], v[3]);
            hv[2] = __floats2half2_rn(v[4], v[5]);
            hv[3] = __floats2half2_rn(v[6], v[7]);
            *(uint4*)&g_gated_h[(size_t)gr * C2 + h * 64 + c8 * 8] = *(uint4*)hv;
#pragma unroll
            for (int j = 0; j < 8; j++) { sum[j] += v[j]; sq[j] += v[j] * v[j]; }
        }
#pragma unroll
        for (int j = 0; j < 8; j++) {
            sum[j] += __shfl_xor_sync(0xffffffffu, sum[j], 8);
            sum[j] += __shfl_xor_sync(0xffffffffu, sum[j], 16);
            sq[j]  += __shfl_xor_sync(0xffffffffu, sq[j], 8);
            sq[j]  += __shfl_xor_sync(0xffffffffu, sq[j], 16);
        }
        if (lane < 8) {
#pragma unroll
            for (int j = 0; j < 8; j++) {
                bredS[w * 64 + lane * 8 + j] = sum[j];
                bredQ[w * 64 + lane * 8 + j] = sq[j];
            }
        }
        __syncthreads();
        if (tid < 64) {
            double t = 0.0;
#pragma unroll
            for (int w8 = 0; w8 < 8; w8++) t += (double)bredS[w8 * 64 + tid];
            atomicAdd(&g_stats[h * 64 + tid], t);
        } else if (tid < 128) {
            int cc = tid - 64;
            double t = 0.0;
#pragma unroll
            for (int w8 = 0; w8 < 8; w8++) t += (double)bredQ[w8 * 64 + cc];
            atomicAdd(&g_stats[128 + h * 64 + cc], t);
        }
    }
}

// ------------------------- finalize BN1 -------------------------
__global__ void finbn1_kernel(const float* __restrict__ g1,
                              const float* __restrict__ be1, int l) {
    int c = threadIdx.x;   // 128 threads
    double inv  = 1.0 / (double)NMROWS;
    double mean = g_stats[c] * inv;
    double var  = g_stats[128 + c] * inv - mean * mean;
    float sc = g1[l * C2 + c] * rsqrtf((float)var + EPSBN);
    g_scale1[c] = sc;
    g_shift1[c] = be1[l * C2 + c] - (float)mean * sc;
}

// ------------------------- sigmoid*softplus message sum + BN2 stats -------------------
__global__ void convreduce_kernel() {
    const int tid = threadIdx.x;          // 256
    const int w = tid >> 5;               // 0..7
    const unsigned lane = tid & 31;
    const float2 sf = *(const float2*)&g_scale1[2 * lane];
    const float2 hf = *(const float2*)&g_shift1[2 * lane];
    const float2 sc = *(const float2*)&g_scale1[64 + 2 * lane];
    const float2 hc = *(const float2*)&g_shift1[64 + 2 * lane];
    const __half2* G = (const __half2*)g_gated_h;   // rows of 64 half2
    float wsum0 = 0.f, wsum1 = 0.f, wsq0 = 0.f, wsq1 = 0.f;
    const int abase = blockIdx.x * 32 + w * 4;
    for (int a0 = 0; a0 < 4; a0++) {
        int a = abase + a0;
        size_t base = (size_t)a * MNBR * 64;
        float s0 = 0.f, s1 = 0.f;
#pragma unroll
        for (int m = 0; m < MNBR; m++) {
            float2 f = __half22float2(G[base + m * 64 + lane]);
            float2 c = __half22float2(G[base + m * 64 + 32 + lane]);
            float gf0 = f.x * sf.x + hf.x;
            float gf1 = f.y * sf.y + hf.y;
            float gc0 = c.x * sc.x + hc.x;
            float gc1 = c.y * sc.y + hc.y;
            s0 += sigmoidf_(gf0) * softplusf_(gc0);
            s1 += sigmoidf_(gf1) * softplusf_(gc1);
        }
        float2 so = {s0, s1};
        *(float2*)&g_s[(size_t)a * 64 + 2 * lane] = so;
        wsum0 += s0; wsum1 += s1;
        wsq0 += s0 * s0; wsq1 += s1 * s1;
    }
    __shared__ float bred[8][64];
    bred[w][2 * lane]     = wsum0;
    bred[w][2 * lane + 1] = wsum1;
    __syncthreads();
    if (tid < 64) {
        double t = 0.0;
#pragma unroll
        for (int ww = 0; ww < 8; ww++) t += (double)bred[ww][tid];
        atomicAdd(&g_stats[256 + tid], t);
    }
    __syncthreads();
    bred[w][2 * lane]     = wsq0;
    bred[w][2 * lane + 1] = wsq1;
    __syncthreads();
    if (tid < 64) {
        double t = 0.0;
#pragma unroll
        for (int ww = 0; ww < 8; ww++) t += (double)bred[ww][tid];
        atomicAdd(&g_stats[320 + tid], t);
    }
}

// ------------------------- finalize BN2 -------------------------
__global__ void finbn2_kernel(const float* __restrict__ g2,
                              const float* __restrict__ be2, int l) {
    int c = threadIdx.x;   // 64 threads
    double inv  = 1.0 / (double)NATOM;
    double mean = g_stats[256 + c] * inv;
    double var  = g_stats[320 + c] * inv - mean * mean;
    float sc = g2[l * AF + c] * rsqrtf((float)var + EPSBN);
    g_scale2[c] = sc;
    g_shift2[c] = be2[l * AF + c] - (float)mean * sc;
}

// ------------------------- residual + softplus -------------------------
__global__ void residual_kernel() {
    int i = blockIdx.x * 256 + threadIdx.x;    // N*AF threads
    int c = i & 63;
    float v = g_x[i] + g_s[i] * g_scale2[c] + g_shift2[c];
    g_x[i] = softplusf_(v);
}

// ------------------------- pooling -------------------------
__global__ void zpool_kernel() {
    int i = blockIdx.x * 256 + threadIdx.x;
    if (i < NSEG * AF) g_pool[i] = 0.f;
    if (i < NSEG) g_cnt[i] = 0.f;
}

__global__ void pool_kernel(const int* __restrict__ cai) {
    int i = blockIdx.x * 256 + threadIdx.x;    // N*AF threads
    int n = i >> 6, c = i & 63;
    int seg = cai[n];
    atomicAdd(&g_pool[seg * 64 + c], g_x[i]);
    if (c == 0) atomicAdd(&g_cnt[seg], 1.0f);
}

// ------------------------- head: crys_fea + 2 MLP heads -------------------------
__global__ void head_kernel(const float* __restrict__ W1, const float* __restrict__ b1,
                            const float* __restrict__ W2, const float* __restrict__ b2,
                            float* __restrict__ out) {
    __shared__ float sa[64];
    __shared__ float rw[4];
    const int b = blockIdx.x, t = threadIdx.x;   // 128 threads
    if (t < 64) {
        float cnt  = g_cnt[b];
        float crys = g_pool[b * 64 + t] / fmaxf(cnt, 1.0f);
        out[NSEG * 2 + b * 64 + t] = crys;       // crys_fea output after (N0,P) block
        sa[t] = softplusf_(crys);
    }
    __syncthreads();
    for (int p = 0; p < 2; p++) {
        float acc = b1[p * 128 + t];
#pragma unroll
        for (int f = 0; f < 64; f++) acc += sa[f] * W1[(p * 64 + f) * 128 + t];
        float pv = softplusf_(acc) * W2[p * 128 + t];
#pragma unroll
        for (int off = 16; off > 0; off >>= 1)
            pv += __shfl_down_sync(0xffffffffu, pv, off);
        if ((t & 31) == 0) rw[t >> 5] = pv;
        __syncthreads();
        if (t == 0) out[b * 2 + p] = rw[0] + rw[1] + rw[2] + rw[3] + b2[p];
        __syncthreads();
    }
}

// ------------------------- launch -------------------------
extern "C" void kernel_launch(void* const* d_in, const int* in_sizes, int n_in,
                              void* d_out, int out_size) {
    const float* atom_fea = (const float*)d_in[0];
    const float* nbr_fea  = (const float*)d_in[1];
    const float* W_embed  = (const float*)d_in[2];
    const float* b_embed  = (const float*)d_in[3];
    const float* conv_W   = (const float*)d_in[4];
    const float* conv_b   = (const float*)d_in[5];
    const float* conv_g1  = (const float*)d_in[6];
    const float* conv_be1 = (const float*)d_in[7];
    const float* conv_g2  = (const float*)d_in[8];
    const float* conv_be2 = (const float*)d_in[9];
    const float* head_W1  = (const float*)d_in[10];
    const float* head_b1  = (const float*)d_in[11];
    const float* head_W2  = (const float*)d_in[12];
    const float* head_b2  = (const float*)d_in[13];
    const int*   nbr_idx  = (const int*)d_in[14];
    const int*   cai      = (const int*)d_in[15];
    float* out = (float*)d_out;

    cudaFuncSetAttribute(convmain_kernel,
                         cudaFuncAttributeMaxDynamicSharedMemorySize, CM_TOTAL);
    cudaFuncSetAttribute(selfnbr_kernel,
                         cudaFuncAttributeMaxDynamicSharedMemorySize, SN_TOTAL);

    embed_kernel<<<NATOM / 128, 256>>>(atom_fea, W_embed, b_embed);
    for (int l = 0; l < NCONVL; l++) {
        selfnbr_kernel<<<dim3(NATOM / 128, 2), 256, SN_TOTAL>>>(conv_W, conv_b, l);
        zstats_kernel<<<1, 384>>>();
        convmain_kernel<<<NMROWS / 128, 256, CM_TOTAL>>>(nbr_fea, nbr_idx, conv_W, l);
        finbn1_kernel<<<1, 128>>>(conv_g1, conv_be1, l);
        convreduce_kernel<<<NATOM / 32, 256>>>();
        finbn2_kernel<<<1, 64>>>(conv_g2, conv_be2, l);
        residual_kernel<<<NATOM * AF / 256, 256>>>();
    }
    zpool_kernel<<<(NSEG * AF + NSEG + 255) / 256, 256>>>();
    pool_kernel<<<NATOM * AF / 256, 256>>>(cai);
    head_kernel<<<NSEG, 128>>>(head_W1, head_b1, head_W2, head_b2, out);
}